// round 4
// baseline (speedup 1.0000x reference)
#include <cuda_runtime.h>
#include <cstddef>

#define BB       32
#define LL       32768
#define CC       128
#define C2       64          // channel pairs (float2)
#define KK       64
#define PADL     31          // SAME, even K: pad_low = (K-1)/2 = 31

#define TL       64          // time-tile per block
#define ROWS     (TL + KK)   // 128 rows incl. halo (need TL-1+63-(-31)+1 = TL+63, round to 128)
#define NTHREADS 256
#define TSUB     4           // time subgroups
#define TT       (TL / TSUB) // 16 outputs per thread
#define SCH      8           // k-chunk

#define SMEM_X_F   (ROWS * CC)          // 8192*... = 128*128 floats
#define SMEM_W_F   (KK * CC)            // 8192 floats
#define SMEM_BYTES ((SMEM_X_F + SMEM_W_F) * 4)   // 98304 B

// Blackwell packed dual-FMA: 2x fp32 FMA per instruction (FFMA2 in SASS).
__device__ __forceinline__ unsigned long long ffma2(unsigned long long a,
                                                    unsigned long long b,
                                                    unsigned long long c) {
    unsigned long long d;
    asm("fma.rn.f32x2 %0, %1, %2, %3;" : "=l"(d) : "l"(a), "l"(b), "l"(c));
    return d;
}

// Accurate cheap tanh: rational exp form + Taylor branch near 0
// (kills the (t-1) cancellation). Error ~1e-6 everywhere.
__device__ __forceinline__ float fast_tanh(float x) {
    float xc = fminf(fmaxf(x, -15.0f), 15.0f);
    float t  = __expf(2.0f * xc);                 // MUFU.EX2 path
    float r  = __fdividef(t - 1.0f, t + 1.0f);    // MUFU.RCP path
    float x2 = x * x;
    float p  = x * (1.0f + x2 * (-0.33333334f + 0.13333334f * x2));
    return (fabsf(x) < 0.05f) ? p : r;
}

__global__ __launch_bounds__(NTHREADS, 2)
void dwconv1d_tanh_kernel(const float* __restrict__ x,
                          const float* __restrict__ w,      // (K,1,C) -> [k][c]
                          const float* __restrict__ bias,   // (C,)
                          float* __restrict__ out) {
    extern __shared__ float sm[];
    float* sx = sm;                  // [ROWS][CC]
    float* sw = sm + SMEM_X_F;       // [KK][CC]

    const int tid  = threadIdx.x;
    const int blk  = blockIdx.x;
    const int b    = blk >> 9;       // 512 tiles per batch (32768/64)
    const int tile = blk & 511;
    const int t0   = tile * TL;

    // ---- stage weights (32 KB) ----
    {
        const float4* wsrc = (const float4*)w;   // 2048 float4
        float4*       wdst = (float4*)sw;
        #pragma unroll
        for (int i = 0; i < (KK * CC / 4) / NTHREADS; i++)   // 8 iters
            wdst[tid + i * NTHREADS] = wsrc[tid + i * NTHREADS];
    }

    // ---- stage x tile rows [t0-31, t0-31+ROWS), zero-padded ----
    {
        const int base = t0 - PADL;
        #pragma unroll
        for (int it = 0; it < ROWS * (CC / 4) / NTHREADS; it++) {  // 16 iters
            int i   = tid + it * NTHREADS;
            int row = i >> 5;        // CC/4 = 32 float4 per row
            int col = i & 31;
            int g   = base + row;
            float4 v = make_float4(0.f, 0.f, 0.f, 0.f);
            if ((unsigned)g < (unsigned)LL)
                v = ((const float4*)x)[((size_t)b * LL + g) * (CC / 4) + col];
            ((float4*)sx)[row * 32 + col] = v;
        }
    }
    __syncthreads();

    const int c2    = tid & (C2 - 1);
    const int ts    = tid >> 6;      // 0..3
    const int jbase = ts * TT;       // local output row offset

    unsigned long long acc[TT];
    #pragma unroll
    for (int j = 0; j < TT; j++) acc[j] = 0ull;

    const unsigned long long* sx2 = ((const unsigned long long*)sx) + c2; // row stride C2
    const unsigned long long* sw2 = ((const unsigned long long*)sw) + c2;

    // out[t][c] = sum_k x[t + k - 31][c] * w[k][c]; shared row r = jlocal + k
    #pragma unroll
    for (int kk = 0; kk < KK; kk += SCH) {
        unsigned long long wr[SCH];
        #pragma unroll
        for (int s = 0; s < SCH; s++) wr[s] = sw2[(kk + s) * C2];

        unsigned long long xr[TT + SCH - 1];
        #pragma unroll
        for (int i = 0; i < TT + SCH - 1; i++) xr[i] = sx2[(jbase + kk + i) * C2];

        #pragma unroll
        for (int s = 0; s < SCH; s++)
            #pragma unroll
            for (int j = 0; j < TT; j++)
                acc[j] = ffma2(xr[j + s], wr[s], acc[j]);
    }

    // ---- bias + tanh + store (coalesced 8B/lane) ----
    const float2 bv = ((const float2*)bias)[c2];
    float2* outp = (float2*)out;
    const size_t obase = ((size_t)b * LL + t0 + jbase) * C2 + c2;
    #pragma unroll
    for (int j = 0; j < TT; j++) {
        float2 a = *(float2*)&acc[j];
        float y0 = fast_tanh(a.x + bv.x);
        float y1 = fast_tanh(a.y + bv.y);
        outp[obase + (size_t)j * C2] = make_float2(y0, y1);
    }
}

extern "C" void kernel_launch(void* const* d_in, const int* in_sizes, int n_in,
                              void* d_out, int out_size) {
    const float* x    = (const float*)d_in[0];
    const float* w    = (const float*)d_in[1];
    const float* bias = (const float*)d_in[2];
    float*       out  = (float*)d_out;

    // Idempotent, deterministic, host-side only (not a stream op) — capture-safe.
    cudaFuncSetAttribute(dwconv1d_tanh_kernel,
                         cudaFuncAttributeMaxDynamicSharedMemorySize, SMEM_BYTES);

    dwconv1d_tanh_kernel<<<BB * (LL / TL), NTHREADS, SMEM_BYTES>>>(x, w, bias, out);
}